// round 4
// baseline (speedup 1.0000x reference)
#include <cuda_runtime.h>
#include <cuda_bf16.h>
#include <float.h>

#define IMG_W   2048
#define IMG_H   2048
#define WM1     2047.0f
#define TPB     128
#define BUILD_TPB 256
#define MAXBLK  4096
#define SPLIT   4          // threads per point

// Quad table: tab[y*2048+x] = {img[y][x], img[y][x1], img[y1][x], img[y1][x1]}
__device__ float4 g_tab[IMG_W * IMG_H];          // 64 MB, L2-resident
__device__ float g_partials[MAXBLK];
__device__ unsigned int g_count;                 // zero-init; wraps via atomicInc

// 4 pixels per thread, float4 in / 4x float4 out (coalesced)
__global__ void __launch_bounds__(BUILD_TPB)
build_tab_kernel(const float* __restrict__ img) {
    int tid = blockIdx.x * BUILD_TPB + threadIdx.x;
    int y  = tid >> 9;                 // 512 groups of 4 per row
    int xg = (tid & 511) << 2;
    int y1 = min(y + 1, IMG_H - 1);
    const float4* r0v = (const float4*)(img + y  * IMG_W);
    const float4* r1v = (const float4*)(img + y1 * IMG_W);
    float4 a = __ldg(&r0v[xg >> 2]);
    float4 c = __ldg(&r1v[xg >> 2]);
    int x4 = min(xg + 4, IMG_W - 1);
    float a4 = __ldg(img + y  * IMG_W + x4);
    float c4 = __ldg(img + y1 * IMG_W + x4);
    float4* dst = &g_tab[y * IMG_W + xg];
    dst[0] = make_float4(a.x, a.y, c.x, c.y);
    dst[1] = make_float4(a.y, a.z, c.y, c.z);
    dst[2] = make_float4(a.z, a.w, c.z, c.w);
    dst[3] = make_float4(a.w, a4,  c.w, c4);
}

__device__ __forceinline__ float bilin_tab(float x, float y) {
    float xf = floorf(x), yf = floorf(y);
    float wx = x - xf,    wy = y - yf;
    int xi = (int)xf, yi = (int)yf;
    float4 q = __ldg(&g_tab[yi * IMG_W + xi]);
    float top = fmaf(wx, q.y - q.x, q.x);
    float bot = fmaf(wx, q.w - q.z, q.z);
    return fmaf(wy, bot - top, top);
}

__global__ void __launch_bounds__(TPB, 14)
contour_loss_kernel(const float* __restrict__ points,
                    const float* __restrict__ normals,
                    float* __restrict__ out,
                    int N, int nblocks, float inv_n) {
    int gtid = blockIdx.x * TPB + threadIdx.x;
    int pt  = gtid >> 2;        // point index
    int sub = gtid & 3;         // segment index within point
    float sq = 0.0f;

    if (pt < N) {
        float px = fminf(fmaxf(__ldg(&points[2 * pt]),     0.0f), WM1);
        float py = fminf(fmaxf(__ldg(&points[2 * pt + 1]), 0.0f), WM1);
        float nx = __ldg(&normals[2 * pt]);
        float ny = __ldg(&normals[2 * pt + 1]);
        float dx = -ny, dy = nx;
        float inv = rsqrtf(dx * dx + dy * dy);
        dx *= inv; dy *= inv;

        float t_left  = (dx != 0.0f) ? (0.0f - px) / dx : -FLT_MAX;
        float t_right = (dx != 0.0f) ? (WM1  - px) / dx :  FLT_MAX;
        float t_top   = (dy != 0.0f) ? (0.0f - py) / dy : -FLT_MAX;
        float t_bot   = (dy != 0.0f) ? (WM1  - py) / dy :  FLT_MAX;
        float t_min = fmaxf(t_left,  t_top);
        float t_max = fminf(t_right, t_bot);

        float p1x = fmaf(t_min, dx, px), p1y = fmaf(t_min, dy, py);
        float p2x = fmaf(t_max, dx, px), p2y = fmaf(t_max, dy, py);
        float vx = p2x - p1x, vy = p2y - p1y;

        const float step = 1.0f / 99.0f;

        // centers this thread owns: [c_lo, c_hi]; needs samples [c_lo-1, c_hi+1]
        int c_lo = 1 + sub * 25;
        int c_hi = min(c_lo + 24, 98);

        float t0 = (float)(c_lo - 1) * step;
        float lx = fminf(fmaxf(fmaf(t0, vx, p1x), 0.0f), WM1);
        float ly = fminf(fmaxf(fmaf(t0, vy, p1y), 0.0f), WM1);
        float v_prev = bilin_tab(lx, ly);

        float t1 = (float)c_lo * step;
        lx = fminf(fmaxf(fmaf(t1, vx, p1x), 0.0f), WM1);
        ly = fminf(fmaxf(fmaf(t1, vy, p1y), 0.0f), WM1);
        float v_cur = bilin_tab(lx, ly);
        float cx = lx, cy = ly;

        // defaults: sub 0 carries vals[1] (argmin of all-inf -> idx 0 -> vals[1])
        float best_dist = FLT_MAX;   // squared distance (argmin-equivalent)
        int   best_idx  = (sub == 0) ? 0x7FFFFFFE : 0x7FFFFFFF;
        float best_val  = (sub == 0) ? v_cur : 0.0f;

        #pragma unroll 6
        for (int s = c_lo; s <= c_hi; s++) {
            float tn  = (float)(s + 1) * step;
            float nlx = fminf(fmaxf(fmaf(tn, vx, p1x), 0.0f), WM1);
            float nly = fminf(fmaxf(fmaf(tn, vy, p1y), 0.0f), WM1);
            float v_next = bilin_tab(nlx, nly);

            if (v_cur < v_prev && v_cur < v_next) {
                float ddx = cx - px, ddy = cy - py;
                float d2 = fmaf(ddx, ddx, ddy * ddy);
                if (d2 < best_dist) {   // ascending s + strict < = first minimum
                    best_dist = d2;
                    best_idx  = s;
                    best_val  = v_cur;
                }
            }
            v_prev = v_cur;
            v_cur  = v_next;
            cx = nlx; cy = nly;
        }

        // combine across the 4 sub-threads (lexicographic on (dist2, idx))
        #pragma unroll
        for (int m = 1; m <= 2; m <<= 1) {
            float od = __shfl_xor_sync(0xFFFFFFFFu, best_dist, m);
            int   oi = __shfl_xor_sync(0xFFFFFFFFu, best_idx,  m);
            float ov = __shfl_xor_sync(0xFFFFFFFFu, best_val,  m);
            if (od < best_dist || (od == best_dist && oi < best_idx)) {
                best_dist = od; best_idx = oi; best_val = ov;
            }
        }

        if (sub == 0) {
            float ref_val = bilin_tab(px, py);
            float diff = best_val - ref_val;
            sq = diff * diff;
        }
    }

    // ── block reduction (deterministic) ──
    __shared__ float smem[TPB / 32];
    __shared__ bool s_last;
    float v = sq;
    #pragma unroll
    for (int off = 16; off > 0; off >>= 1)
        v += __shfl_down_sync(0xFFFFFFFFu, v, off);
    int lane = threadIdx.x & 31;
    int wid  = threadIdx.x >> 5;
    if (lane == 0) smem[wid] = v;
    __syncthreads();
    if (wid == 0) {
        v = (lane < TPB / 32) ? smem[lane] : 0.0f;
        #pragma unroll
        for (int off = 2; off > 0; off >>= 1)
            v += __shfl_down_sync(0xFFFFFFFFu, v, off);
        if (lane == 0) {
            g_partials[blockIdx.x] = v;
            __threadfence();
            unsigned int t = atomicInc(&g_count, (unsigned int)(nblocks - 1));
            s_last = (t == (unsigned int)(nblocks - 1));
        }
    }
    __syncthreads();

    // ── last block sums partials (fixed strided order => deterministic) ──
    if (s_last) {
        float acc = 0.0f;
        for (int k = threadIdx.x; k < nblocks; k += TPB)
            acc += g_partials[k];
        #pragma unroll
        for (int off = 16; off > 0; off >>= 1)
            acc += __shfl_down_sync(0xFFFFFFFFu, acc, off);
        if (lane == 0) smem[wid] = acc;
        __syncthreads();
        if (wid == 0) {
            acc = (lane < TPB / 32) ? smem[lane] : 0.0f;
            #pragma unroll
            for (int off = 2; off > 0; off >>= 1)
                acc += __shfl_down_sync(0xFFFFFFFFu, acc, off);
            if (lane == 0) out[0] = acc * inv_n;
        }
    }
}

extern "C" void kernel_launch(void* const* d_in, const int* in_sizes, int n_in,
                              void* d_out, int out_size) {
    const float* img     = (const float*)d_in[0];
    const float* points  = (const float*)d_in[1];
    const float* normals = (const float*)d_in[2];
    float* out = (float*)d_out;

    int N = in_sizes[1] / 2;
    int total = N * SPLIT;
    int blocks = (total + TPB - 1) / TPB;

    build_tab_kernel<<<(IMG_W * (IMG_W / 4)) / BUILD_TPB, BUILD_TPB>>>(img);
    contour_loss_kernel<<<blocks, TPB>>>(points, normals, out, N, blocks,
                                         1.0f / (float)N);
}

// round 5
// speedup vs baseline: 1.0784x; 1.0784x over previous
#include <cuda_runtime.h>
#include <cuda_bf16.h>
#include <float.h>

#define IMG_W   2048
#define IMG_H   2048
#define WM1     2047.0f
#define TPB     128
#define BUILD_TPB 256
#define MAXBLK  4096
#define SPLIT   4          // threads per point

// Quad table: tab[y*2048+x] = {img[y][x], img[y][x1], img[y1][x], img[y1][x1]}
__device__ float4 g_tab[IMG_W * IMG_H];          // 64 MB
__device__ float g_partials[MAXBLK];
__device__ unsigned int g_count;                 // zero-init; wraps via atomicInc

// 4 pixels per thread, float4 in / 4x float4 out (coalesced)
__global__ void __launch_bounds__(BUILD_TPB)
build_tab_kernel(const float* __restrict__ img) {
    int tid = blockIdx.x * BUILD_TPB + threadIdx.x;
    int y  = tid >> 9;                 // 512 groups of 4 per row
    int xg = (tid & 511) << 2;
    int y1 = min(y + 1, IMG_H - 1);
    const float4* r0v = (const float4*)(img + y  * IMG_W);
    const float4* r1v = (const float4*)(img + y1 * IMG_W);
    float4 a = __ldg(&r0v[xg >> 2]);
    float4 c = __ldg(&r1v[xg >> 2]);
    int x4 = min(xg + 4, IMG_W - 1);
    float a4 = __ldg(img + y  * IMG_W + x4);
    float c4 = __ldg(img + y1 * IMG_W + x4);
    float4* dst = &g_tab[y * IMG_W + xg];
    dst[0] = make_float4(a.x, a.y, c.x, c.y);
    dst[1] = make_float4(a.y, a.z, c.y, c.z);
    dst[2] = make_float4(a.z, a.w, c.z, c.w);
    dst[3] = make_float4(a.w, a4,  c.w, c4);
}

__device__ __forceinline__ float bilin_tab(float x, float y) {
    float xf = floorf(x), yf = floorf(y);
    float wx = x - xf,    wy = y - yf;
    int xi = (int)xf, yi = (int)yf;
    float4 q = __ldg(&g_tab[yi * IMG_W + xi]);
    float top = fmaf(wx, q.y - q.x, q.x);
    float bot = fmaf(wx, q.w - q.z, q.z);
    return fmaf(wy, bot - top, top);
}

__global__ void __launch_bounds__(TPB)
contour_loss_kernel(const float* __restrict__ points,
                    const float* __restrict__ normals,
                    float* __restrict__ out,
                    int N, int nblocks, float inv_n) {
    int gtid = blockIdx.x * TPB + threadIdx.x;
    int pt  = gtid >> 2;        // point index
    int sub = gtid & 3;         // segment index within point
    float sq = 0.0f;

    if (pt < N) {
        float px = fminf(fmaxf(__ldg(&points[2 * pt]),     0.0f), WM1);
        float py = fminf(fmaxf(__ldg(&points[2 * pt + 1]), 0.0f), WM1);
        float nx = __ldg(&normals[2 * pt]);
        float ny = __ldg(&normals[2 * pt + 1]);
        float dx = -ny, dy = nx;
        float inv = rsqrtf(dx * dx + dy * dy);
        dx *= inv; dy *= inv;

        float t_left  = (dx != 0.0f) ? (0.0f - px) / dx : -FLT_MAX;
        float t_right = (dx != 0.0f) ? (WM1  - px) / dx :  FLT_MAX;
        float t_top   = (dy != 0.0f) ? (0.0f - py) / dy : -FLT_MAX;
        float t_bot   = (dy != 0.0f) ? (WM1  - py) / dy :  FLT_MAX;
        float t_min = fmaxf(t_left,  t_top);
        float t_max = fminf(t_right, t_bot);

        float p1x = fmaf(t_min, dx, px), p1y = fmaf(t_min, dy, py);
        float p2x = fmaf(t_max, dx, px), p2y = fmaf(t_max, dy, py);
        float vx = p2x - p1x, vy = p2y - p1y;

        const float step = 1.0f / 99.0f;

        // centers this thread owns: [c_lo, c_hi]; needs samples [c_lo-1, c_hi+1]
        int c_lo = 1 + sub * 25;
        int c_hi = min(c_lo + 24, 98);

        float t0 = (float)(c_lo - 1) * step;
        float lx = fminf(fmaxf(fmaf(t0, vx, p1x), 0.0f), WM1);
        float ly = fminf(fmaxf(fmaf(t0, vy, p1y), 0.0f), WM1);
        float v_prev = bilin_tab(lx, ly);

        float t1 = (float)c_lo * step;
        lx = fminf(fmaxf(fmaf(t1, vx, p1x), 0.0f), WM1);
        ly = fminf(fmaxf(fmaf(t1, vy, p1y), 0.0f), WM1);
        float v_cur = bilin_tab(lx, ly);
        float cx = lx, cy = ly;

        // defaults: sub 0 carries vals[1] (argmin of all-inf -> idx 0 -> vals[1])
        float best_dist = FLT_MAX;   // squared distance (argmin-equivalent)
        int   best_idx  = (sub == 0) ? 0x7FFFFFFE : 0x7FFFFFFF;
        float best_val  = (sub == 0) ? v_cur : 0.0f;

        #pragma unroll 5
        for (int s = c_lo; s <= c_hi; s++) {
            float tn  = (float)(s + 1) * step;
            float nlx = fminf(fmaxf(fmaf(tn, vx, p1x), 0.0f), WM1);
            float nly = fminf(fmaxf(fmaf(tn, vy, p1y), 0.0f), WM1);
            float v_next = bilin_tab(nlx, nly);

            // branchless minima + argmin update (keeps body straight-line so
            // ptxas front-batches the unrolled group's LDGs)
            float ddx = cx - px, ddy = cy - py;
            float d2 = fmaf(ddx, ddx, ddy * ddy);
            bool is_min = (v_cur < v_prev) & (v_cur < v_next);
            float cand = is_min ? d2 : FLT_MAX;
            bool upd = cand < best_dist;      // ascending s + strict < = first min
            best_dist = upd ? cand  : best_dist;
            best_idx  = upd ? s     : best_idx;
            best_val  = upd ? v_cur : best_val;

            v_prev = v_cur;
            v_cur  = v_next;
            cx = nlx; cy = nly;
        }

        // combine across the 4 sub-threads (lexicographic on (dist2, idx))
        #pragma unroll
        for (int m = 1; m <= 2; m <<= 1) {
            float od = __shfl_xor_sync(0xFFFFFFFFu, best_dist, m);
            int   oi = __shfl_xor_sync(0xFFFFFFFFu, best_idx,  m);
            float ov = __shfl_xor_sync(0xFFFFFFFFu, best_val,  m);
            if (od < best_dist || (od == best_dist && oi < best_idx)) {
                best_dist = od; best_idx = oi; best_val = ov;
            }
        }

        if (sub == 0) {
            float ref_val = bilin_tab(px, py);
            float diff = best_val - ref_val;
            sq = diff * diff;
        }
    }

    // ── block reduction (deterministic) ──
    __shared__ float smem[TPB / 32];
    __shared__ bool s_last;
    float v = sq;
    #pragma unroll
    for (int off = 16; off > 0; off >>= 1)
        v += __shfl_down_sync(0xFFFFFFFFu, v, off);
    int lane = threadIdx.x & 31;
    int wid  = threadIdx.x >> 5;
    if (lane == 0) smem[wid] = v;
    __syncthreads();
    if (wid == 0) {
        v = (lane < TPB / 32) ? smem[lane] : 0.0f;
        #pragma unroll
        for (int off = 2; off > 0; off >>= 1)
            v += __shfl_down_sync(0xFFFFFFFFu, v, off);
        if (lane == 0) {
            g_partials[blockIdx.x] = v;
            __threadfence();
            unsigned int t = atomicInc(&g_count, (unsigned int)(nblocks - 1));
            s_last = (t == (unsigned int)(nblocks - 1));
        }
    }
    __syncthreads();

    // ── last block sums partials (fixed strided order => deterministic) ──
    if (s_last) {
        float acc = 0.0f;
        for (int k = threadIdx.x; k < nblocks; k += TPB)
            acc += g_partials[k];
        #pragma unroll
        for (int off = 16; off > 0; off >>= 1)
            acc += __shfl_down_sync(0xFFFFFFFFu, acc, off);
        if (lane == 0) smem[wid] = acc;
        __syncthreads();
        if (wid == 0) {
            acc = (lane < TPB / 32) ? smem[lane] : 0.0f;
            #pragma unroll
            for (int off = 2; off > 0; off >>= 1)
                acc += __shfl_down_sync(0xFFFFFFFFu, acc, off);
            if (lane == 0) out[0] = acc * inv_n;
        }
    }
}

extern "C" void kernel_launch(void* const* d_in, const int* in_sizes, int n_in,
                              void* d_out, int out_size) {
    const float* img     = (const float*)d_in[0];
    const float* points  = (const float*)d_in[1];
    const float* normals = (const float*)d_in[2];
    float* out = (float*)d_out;

    int N = in_sizes[1] / 2;
    int total = N * SPLIT;
    int blocks = (total + TPB - 1) / TPB;

    build_tab_kernel<<<(IMG_W * (IMG_W / 4)) / BUILD_TPB, BUILD_TPB>>>(img);
    contour_loss_kernel<<<blocks, TPB>>>(points, normals, out, N, blocks,
                                         1.0f / (float)N);
}